// round 17
// baseline (speedup 1.0000x reference)
#include <cuda_runtime.h>

#define NN   100000
#define EE   3200000
#define IND  128
#define OUTD 64

// Scratch (device globals — no allocation allowed)
__device__ float g_h[NN * OUTD];      // 25.6 MB
__device__ float g_hs[NN];
__device__ float g_ht[NN];
__device__ int   g_deg[NN];
__device__ int   g_off[NN + 1];
__device__ int   g_rank[EE];          // within-bucket rank of each edge
__device__ int2  g_sp[EE];            // {src, bitcast(p)} permuted by target
__device__ int   g_is64;              // 1 if edge_index is int64, 0 if int32

__device__ __forceinline__ int clampi(int v) {
    return min(max(v, 0), NN - 1);
}

// ---------------------------------------------------------------------------
// Fused: zero the degree histogram + detect edge_index dtype (block 0, warp 0)
// ---------------------------------------------------------------------------
__global__ void zero_detect_kernel(const int* __restrict__ ei_raw) {
    int i = blockIdx.x * blockDim.x + threadIdx.x;
    if (i < NN) g_deg[i] = 0;
    if (blockIdx.x == 0 && threadIdx.x < 32) {
        int lane = threadIdx.x;
        int nz = 0;
        #pragma unroll
        for (int k = 0; k < 4; ++k) nz |= __ldg(ei_raw + 2 * (lane * 4 + k) + 1);
        unsigned m = __ballot_sync(0xFFFFFFFFu, nz != 0);
        if (lane == 0) g_is64 = (m == 0);
    }
}

// ---------------------------------------------------------------------------
// h = x @ W  fused with  hs = h@a_src, ht = h@a_tgt.
// Block 256: 16 threads per row (4 cols each), 16 rows per tile, 4 tiles.
// ---------------------------------------------------------------------------
__global__ __launch_bounds__(256) void gemm_attn_kernel(const float* __restrict__ x,
                                                        const float* __restrict__ W,
                                                        const float* __restrict__ a_src,
                                                        const float* __restrict__ a_tgt) {
    __shared__ float4 Ws4[IND * 16];   // 32 KB
    __shared__ float  xs[16 * IND];    // 8 KB
    __shared__ float  as_s[OUTD], at_s[OUTD];

    const int tid = threadIdx.x;
    for (int i = tid; i < IND * 16; i += 256)
        Ws4[i] = reinterpret_cast<const float4*>(W)[i];
    if (tid < OUTD) { as_s[tid] = a_src[tid]; at_s[tid] = a_tgt[tid]; }

    const int r  = tid >> 4;           // 0..15 row-in-tile
    const int cg = tid & 15;           // 0..15 col-group (4 cols)
    const int rowBase = blockIdx.x * 64;

    for (int it = 0; it < 4; ++it) {
        const int r0 = rowBase + it * 16;
        __syncthreads();
        for (int i = tid; i < 16 * IND / 4; i += 256) {
            int rr = r0 + (i * 4) / IND;
            float4 v = make_float4(0.f, 0.f, 0.f, 0.f);
            if (rr < NN)
                v = reinterpret_cast<const float4*>(x)[(size_t)r0 * (IND / 4) + i];
            reinterpret_cast<float4*>(xs)[i] = v;
        }
        __syncthreads();

        float4 acc = make_float4(0.f, 0.f, 0.f, 0.f);
        const float* xr = xs + r * IND;
        #pragma unroll 8
        for (int k = 0; k < IND; ++k) {
            float  xv = xr[k];
            float4 wv = Ws4[k * 16 + cg];
            acc.x += xv * wv.x;
            acc.y += xv * wv.y;
            acc.z += xv * wv.z;
            acc.w += xv * wv.w;
        }
        const int row = r0 + r;
        if (row < NN)
            reinterpret_cast<float4*>(g_h)[(size_t)row * 16 + cg] = acc;

        float ps = acc.x * as_s[cg * 4] + acc.y * as_s[cg * 4 + 1]
                 + acc.z * as_s[cg * 4 + 2] + acc.w * as_s[cg * 4 + 3];
        float pt = acc.x * at_s[cg * 4] + acc.y * at_s[cg * 4 + 1]
                 + acc.z * at_s[cg * 4 + 2] + acc.w * at_s[cg * 4 + 3];
        #pragma unroll
        for (int o = 8; o; o >>= 1) {
            ps += __shfl_xor_sync(0xFFFFFFFFu, ps, o, 16);
            pt += __shfl_xor_sync(0xFFFFFFFFu, pt, o, 16);
        }
        if (cg == 0 && row < NN) { g_hs[row] = ps; g_ht[row] = pt; }
    }
}

// ---------------------------------------------------------------------------
// Degree histogram over targets — 8 edges/thread for atomic-latency hiding;
// also records each edge's within-bucket rank (atomic return), so permute
// needs NO atomics.
// ---------------------------------------------------------------------------
__global__ __launch_bounds__(256) void hist_kernel(const void* __restrict__ ei) {
    int q = blockIdx.x * blockDim.x + threadIdx.x;   // octet index
    if (q >= EE / 8) return;
    int t[8];
    if (g_is64) {
        const long long* p = (const long long*)ei + EE + (size_t)q * 8;
        #pragma unroll
        for (int i = 0; i < 8; ++i) t[i] = clampi((int)p[i]);
    } else {
        int4 a = __ldg((const int4*)((const int*)ei + EE) + q * 2);
        int4 b = __ldg((const int4*)((const int*)ei + EE) + q * 2 + 1);
        t[0] = clampi(a.x); t[1] = clampi(a.y); t[2] = clampi(a.z); t[3] = clampi(a.w);
        t[4] = clampi(b.x); t[5] = clampi(b.y); t[6] = clampi(b.z); t[7] = clampi(b.w);
    }
    int r[8];
    #pragma unroll
    for (int i = 0; i < 8; ++i) r[i] = atomicAdd(&g_deg[t[i]], 1);
    reinterpret_cast<int4*>(g_rank)[q * 2]     = make_int4(r[0], r[1], r[2], r[3]);
    reinterpret_cast<int4*>(g_rank)[q * 2 + 1] = make_int4(r[4], r[5], r[6], r[7]);
}

// ---------------------------------------------------------------------------
// Exclusive scan of g_deg -> g_off (single block, 1024 threads, chunked)
// ---------------------------------------------------------------------------
__global__ __launch_bounds__(1024) void scan_kernel() {
    __shared__ int partial[1024];
    const int CH  = (NN + 1023) / 1024;        // 98
    const int tid = threadIdx.x;
    const int begin = tid * CH;
    const int end   = min(begin + CH, NN);

    int sum = 0;
    for (int i = begin; i < end; ++i) sum += g_deg[i];
    partial[tid] = sum;
    __syncthreads();

    for (int off = 1; off < 1024; off <<= 1) {
        int v = (tid >= off) ? partial[tid - off] : 0;
        __syncthreads();
        partial[tid] += v;
        __syncthreads();
    }

    int run = (tid == 0) ? 0 : partial[tid - 1];
    for (int i = begin; i < end; ++i) { g_off[i] = run; run += g_deg[i]; }
    if (tid == 1023) g_off[NN] = run;          // == EE
}

// ---------------------------------------------------------------------------
// Permute edges into target-sorted buckets (atomic-free), 8 edges/thread:
//   g_sp[g_off[t] + rank[e]] = {src, p},  p = exp(lrelu(hs[s]+ht[t])*w)
// ---------------------------------------------------------------------------
__global__ __launch_bounds__(256) void permute_kernel(const void* __restrict__ ei,
                                                      const float* __restrict__ w) {
    int q = blockIdx.x * blockDim.x + threadIdx.x;
    if (q >= EE / 8) return;

    int s[8], t[8];
    if (g_is64) {
        const long long* ps = (const long long*)ei + (size_t)q * 8;
        const long long* pt = (const long long*)ei + EE + (size_t)q * 8;
        #pragma unroll
        for (int i = 0; i < 8; ++i) { s[i] = clampi((int)ps[i]); t[i] = clampi((int)pt[i]); }
    } else {
        int4 sa = __ldg((const int4*)ei + q * 2);
        int4 sb = __ldg((const int4*)ei + q * 2 + 1);
        int4 ta = __ldg((const int4*)((const int*)ei + EE) + q * 2);
        int4 tb = __ldg((const int4*)((const int*)ei + EE) + q * 2 + 1);
        s[0] = clampi(sa.x); s[1] = clampi(sa.y); s[2] = clampi(sa.z); s[3] = clampi(sa.w);
        s[4] = clampi(sb.x); s[5] = clampi(sb.y); s[6] = clampi(sb.z); s[7] = clampi(sb.w);
        t[0] = clampi(ta.x); t[1] = clampi(ta.y); t[2] = clampi(ta.z); t[3] = clampi(ta.w);
        t[4] = clampi(tb.x); t[5] = clampi(tb.y); t[6] = clampi(tb.z); t[7] = clampi(tb.w);
    }
    float4 wa = __ldg((const float4*)w + q * 2);
    float4 wb = __ldg((const float4*)w + q * 2 + 1);
    float ww[8] = {wa.x, wa.y, wa.z, wa.w, wb.x, wb.y, wb.z, wb.w};
    int4 ra = __ldg((const int4*)g_rank + q * 2);
    int4 rb = __ldg((const int4*)g_rank + q * 2 + 1);
    int rr[8] = {ra.x, ra.y, ra.z, ra.w, rb.x, rb.y, rb.z, rb.w};

    float hsv[8], htv[8];
    #pragma unroll
    for (int i = 0; i < 8; ++i) { hsv[i] = g_hs[s[i]]; htv[i] = g_ht[t[i]]; }

    #pragma unroll
    for (int i = 0; i < 8; ++i) {
        float v = hsv[i] + htv[i];
        v = v > 0.f ? v : 0.2f * v;
        v *= ww[i];
        float p = __expf(v);
        g_sp[g_off[t[i]] + rr[i]] = make_int2(s[i], __float_as_int(p));
    }
}

// ---------------------------------------------------------------------------
// Gather: one warp per target node; TWO edges per iteration.
// Lanes 0-15 process edge A's 64-float row as float4, lanes 16-31 edge B.
// One LDG.128 covers both edges (512B). Cross-half shfl_xor(16) combines.
// ---------------------------------------------------------------------------
__global__ __launch_bounds__(256) void gather_kernel(float* __restrict__ out) {
    __shared__ int2 ds[8][32];
    const int wIdx = threadIdx.x >> 5;
    const int lane = threadIdx.x & 31;
    const int half = lane >> 4;        // 0: edge A, 1: edge B
    const int le   = lane & 15;        // float4 slot within the row
    const int t    = blockIdx.x * 8 + wIdx;
    if (t >= NN) return;

    const int base = g_off[t];
    const int end  = g_off[t + 1];

    float  psum = 0.f;
    float4 a = make_float4(0.f, 0.f, 0.f, 0.f);

    for (int cbase = base; cbase < end; cbase += 32) {
        const int n = min(32, end - cbase);
        int2 my = make_int2(0, 0);                       // p bitcast 0.0f
        if (lane < n) my = __ldg(&g_sp[cbase + lane]);
        psum += __int_as_float(my.y);
        ds[wIdx][lane] = my;
        __syncwarp();

        int k = 0;
        #pragma unroll 8
        for (; k + 2 <= n; k += 2) {
            int2 d  = ds[wIdx][k + half];
            float p = __int_as_float(d.y);
            float4 hv = __ldg(reinterpret_cast<const float4*>(g_h + (size_t)d.x * OUTD) + le);
            a.x += p * hv.x;
            a.y += p * hv.y;
            a.z += p * hv.z;
            a.w += p * hv.w;
        }
        if (k < n) {                                     // odd tail
            int2 d  = ds[wIdx][k];
            float p = half ? 0.f : __int_as_float(d.y);
            float4 hv = __ldg(reinterpret_cast<const float4*>(g_h + (size_t)d.x * OUTD) + le);
            a.x += p * hv.x;
            a.y += p * hv.y;
            a.z += p * hv.z;
            a.w += p * hv.w;
        }
        __syncwarp();
    }

    // combine the two halves (edge-A accumulator + edge-B accumulator)
    a.x += __shfl_xor_sync(0xFFFFFFFFu, a.x, 16);
    a.y += __shfl_xor_sync(0xFFFFFFFFu, a.y, 16);
    a.z += __shfl_xor_sync(0xFFFFFFFFu, a.z, 16);
    a.w += __shfl_xor_sync(0xFFFFFFFFu, a.w, 16);

    #pragma unroll
    for (int o = 16; o; o >>= 1)
        psum += __shfl_xor_sync(0xFFFFFFFFu, psum, o);
    const float inv = 1.0f / (psum + 1e-10f);

    if (half == 0)
        reinterpret_cast<float4*>(out)[(size_t)t * 16 + le] =
            make_float4(a.x * inv, a.y * inv, a.z * inv, a.w * inv);
}

// ---------------------------------------------------------------------------
extern "C" void kernel_launch(void* const* d_in, const int* in_sizes, int n_in,
                              void* d_out, int out_size) {
    const float* x      = (const float*)d_in[0];
    const void*  ei     = d_in[1];
    const float* ew     = (const float*)d_in[2];
    const float* W      = (const float*)d_in[3];
    const float* a_src  = (const float*)d_in[4];
    const float* a_tgt  = (const float*)d_in[5];
    float*       out    = (float*)d_out;

    zero_detect_kernel<<<(NN + 255) / 256, 256>>>((const int*)ei);
    gemm_attn_kernel<<<(NN + 63) / 64, 256>>>(x, W, a_src, a_tgt);
    hist_kernel<<<(EE / 8 + 255) / 256, 256>>>(ei);
    scan_kernel<<<1, 1024>>>();
    permute_kernel<<<(EE / 8 + 255) / 256, 256>>>(ei, ew);
    gather_kernel<<<(NN + 7) / 8, 256>>>(out);
}